// round 4
// baseline (speedup 1.0000x reference)
#include <cuda_runtime.h>
#include <math.h>

#define NMAX 50000
#define EMAX 1600000
#define H 64

// ---------------- scratch (static device globals; no allocation) ----------------
__device__ int   g_deg[NMAX];
__device__ int   g_rowcnt[NMAX];
__device__ int   g_rowptr[NMAX + 1];
__device__ int   g_fill[NMAX];
__device__ float g_dinv[NMAX];
__device__ int2  g_colval[EMAX];          // interleaved (col, val-bits): one 8B load
__device__ int   g_bsum[256];
__device__ int   g_boff[256];
__device__ float g_h[NMAX * H];
__device__ float g_h0[NMAX * H];
__device__ float g_tmp[NMAX * H];
__device__ float g_A[NMAX * H];
__device__ float g_B[NMAX * H];

// ---------------- setup kernels ----------------
__global__ void k_count(const int* __restrict__ ei, int e_cnt) {
    int e = blockIdx.x * blockDim.x + threadIdx.x;
    if (e < e_cnt) {
        atomicAdd(&g_deg[ei[e_cnt + e]], 1);   // deg over col (edge_index[1])
        atomicAdd(&g_rowcnt[ei[e]], 1);        // CSR histogram over row (edge_index[0])
    }
}

__global__ void k_dinv(int n) {
    int i = blockIdx.x * blockDim.x + threadIdx.x;
    if (i < n) g_dinv[i] = rsqrtf((float)(g_deg[i] + 1));   // +1 = self-loop
}

// ---- 3-phase parallel exclusive scan of g_rowcnt -> g_rowptr ----
__global__ void k_scan1(int n) {                 // block-local exclusive scan, block=256
    __shared__ int ws[8];
    int i = blockIdx.x * 256 + threadIdx.x;
    int lane = threadIdx.x & 31, wid = threadIdx.x >> 5;
    int v = (i < n) ? g_rowcnt[i] : 0;
    int x = v;
    #pragma unroll
    for (int o = 1; o < 32; o <<= 1) {
        int y = __shfl_up_sync(0xffffffffu, x, o);
        if (lane >= o) x += y;
    }
    if (lane == 31) ws[wid] = x;
    __syncthreads();
    int add = 0;
    for (int k = 0; k < wid; k++) add += ws[k];
    int excl = x - v + add;
    if (i < n) g_rowptr[i] = excl;
    if (threadIdx.x == 255) g_bsum[blockIdx.x] = excl + v;  // block total
}

__global__ void k_scan2(int nb, int total, int n) {  // 1 block, exclusive scan of block sums
    __shared__ int ws[8];
    int t = threadIdx.x, lane = t & 31, wid = t >> 5;
    int v = (t < nb) ? g_bsum[t] : 0;
    int x = v;
    #pragma unroll
    for (int o = 1; o < 32; o <<= 1) {
        int y = __shfl_up_sync(0xffffffffu, x, o);
        if (lane >= o) x += y;
    }
    if (lane == 31) ws[wid] = x;
    __syncthreads();
    int add = 0;
    for (int k = 0; k < wid; k++) add += ws[k];
    if (t < nb) g_boff[t] = x - v + add;
    if (t == 0) g_rowptr[n] = total;
}

__global__ void k_scan3(int n) {
    int i = blockIdx.x * 256 + threadIdx.x;
    if (i < n) {
        int r = g_rowptr[i] + g_boff[blockIdx.x];
        g_rowptr[i] = r;
        g_fill[i] = r;
    }
}

__global__ void k_csr_fill(const int* __restrict__ ei, int e_cnt) {
    int e = blockIdx.x * blockDim.x + threadIdx.x;
    if (e < e_cnt) {
        int r = ei[e], c = ei[e_cnt + e];
        int p = atomicAdd(&g_fill[r], 1);
        g_colval[p] = make_int2(c, __float_as_int(g_dinv[r] * g_dinv[c]));
    }
}

// ---------------- dense 64x64 GEMM (input linear): out = relu(in@W + bias) -------
__global__ void k_gemm64(const float* __restrict__ in, const float* __restrict__ W,
                         const float* __restrict__ bias, float* __restrict__ out,
                         float* __restrict__ out2, int n) {
    __shared__ float sW[64 * 64];
    for (int i = threadIdx.x; i < 4096; i += blockDim.x) sW[i] = W[i];
    __syncthreads();
    int lane = threadIdx.x & 31, warp = threadIdx.x >> 5;
    const float2* in2 = (const float2*)in;
    const float2* sW2 = (const float2*)sW;
    float2 b = ((const float2*)bias)[lane];
    int base = (blockIdx.x * 8 + warp) * 8;
    for (int rr = 0; rr < 8; rr++) {
        int row = base + rr;
        if (row >= n) break;
        float2 rv = in2[row * 32 + lane];
        float a0 = 0.f, a1 = 0.f;
        #pragma unroll
        for (int s = 0; s < 32; s++) {
            float vx = __shfl_sync(0xffffffffu, rv.x, s);
            float vy = __shfl_sync(0xffffffffu, rv.y, s);
            float2 w0 = sW2[(2 * s) * 32 + lane];
            float2 w1 = sW2[(2 * s + 1) * 32 + lane];
            a0 = fmaf(vx, w0.x, fmaf(vy, w1.x, a0));
            a1 = fmaf(vx, w0.y, fmaf(vy, w1.y, a1));
        }
        float2 o = make_float2(fmaxf(a0 + b.x, 0.f), fmaxf(a1 + b.y, 0.f));
        ((float2*)out)[row * 32 + lane] = o;
        ((float2*)out2)[row * 32 + lane] = o;
    }
}

// ------- fused layer: hout = relu((1-beta)*mix + beta*(mix@W)),
//         mix = 0.9*(A_hat @ hin) + 0.1*h0.  Warp per node, persistent grid. -------
__global__ void k_layer(const float* __restrict__ hin, float* __restrict__ hout,
                        const float* __restrict__ W, float beta, int n) {
    __shared__ float sW[64 * 64];
    for (int i = threadIdx.x; i < 4096; i += blockDim.x) sW[i] = W[i];
    __syncthreads();
    int lane = threadIdx.x & 31;
    int gw = (blockIdx.x * blockDim.x + threadIdx.x) >> 5;
    int nw = (gridDim.x * blockDim.x) >> 5;
    const float2* h2 = (const float2*)hin;
    const float2* h02 = (const float2*)g_h0;
    const float2* sW2 = (const float2*)sW;
    float cs = 1.0f - beta;

    for (int node = gw; node < n; node += nw) {
        float di = g_dinv[node];
        float2 hv = h2[node * 32 + lane];
        float ax = di * di * hv.x;
        float ay = di * di * hv.y;
        int e0 = g_rowptr[node], e1 = g_rowptr[node + 1];
        // cooperative chunked gather: 32 (col,val) pairs loaded in 1 instr,
        // then 32 unrolled, independent 256B gathers of hin.
        for (int e = e0; e < e1; e += 32) {
            int rem = e1 - e;
            int2 cv = make_int2(0, 0);
            if (lane < rem) cv = g_colval[e + lane];
            #pragma unroll
            for (int i = 0; i < 32; i++) {
                if (i >= rem) break;
                int   c = __shfl_sync(0xffffffffu, cv.x, i);
                float v = __int_as_float(__shfl_sync(0xffffffffu, cv.y, i));
                float2 xv = h2[c * 32 + lane];
                ax = fmaf(v, xv.x, ax);
                ay = fmaf(v, xv.y, ay);
            }
        }
        float2 h0v = h02[node * 32 + lane];
        float mx = 0.9f * ax + 0.1f * h0v.x;
        float my = 0.9f * ay + 0.1f * h0v.y;
        // GEMM on this node's mix row (shfl broadcast, W in smem)
        float a0 = 0.f, a1 = 0.f;
        #pragma unroll
        for (int s = 0; s < 32; s++) {
            float vx = __shfl_sync(0xffffffffu, mx, s);
            float vy = __shfl_sync(0xffffffffu, my, s);
            float2 w0 = sW2[(2 * s) * 32 + lane];
            float2 w1 = sW2[(2 * s + 1) * 32 + lane];
            a0 = fmaf(vx, w0.x, fmaf(vy, w1.x, a0));
            a1 = fmaf(vx, w0.y, fmaf(vy, w1.y, a1));
        }
        float o0 = fmaxf(cs * mx + beta * a0, 0.f);
        float o1 = fmaxf(cs * my + beta * a1, 0.f);
        ((float2*)hout)[node * 32 + lane] = make_float2(o0, o1);
    }
}

// ---------------- fused A/B projection: A = h@W1[:64], B = h@W1[64:] ----------------
__global__ void k_ab(const float* __restrict__ h, const float* __restrict__ W1, int n) {
    __shared__ float sW[8192];
    for (int i = threadIdx.x; i < 8192; i += blockDim.x) sW[i] = W1[i];
    __syncthreads();
    int lane = threadIdx.x & 31;
    int gw = (blockIdx.x * blockDim.x + threadIdx.x) >> 5;
    int nw = (gridDim.x * blockDim.x) >> 5;
    const float2* h2 = (const float2*)h;
    const float2* sWA2 = (const float2*)sW;
    const float2* sWB2 = (const float2*)(sW + 4096);
    for (int row = gw; row < n; row += nw) {
        float2 rv = h2[row * 32 + lane];
        float a0 = 0.f, a1 = 0.f, b0 = 0.f, b1 = 0.f;
        #pragma unroll
        for (int s = 0; s < 32; s++) {
            float vx = __shfl_sync(0xffffffffu, rv.x, s);
            float vy = __shfl_sync(0xffffffffu, rv.y, s);
            float2 wa0 = sWA2[(2 * s) * 32 + lane];
            float2 wa1 = sWA2[(2 * s + 1) * 32 + lane];
            float2 wb0 = sWB2[(2 * s) * 32 + lane];
            float2 wb1 = sWB2[(2 * s + 1) * 32 + lane];
            a0 = fmaf(vx, wa0.x, fmaf(vy, wa1.x, a0));
            a1 = fmaf(vx, wa0.y, fmaf(vy, wa1.y, a1));
            b0 = fmaf(vx, wb0.x, fmaf(vy, wb1.x, b0));
            b1 = fmaf(vx, wb0.y, fmaf(vy, wb1.y, b1));
        }
        ((float2*)g_A)[row * 32 + lane] = make_float2(a0, a1);
        ((float2*)g_B)[row * 32 + lane] = make_float2(b0, b1);
    }
}

// ---------------- edge MLP: z=A[src]+B[dst]+b1 -> LN -> relu -> @W2+b2 ----------------
__global__ void k_edge(const int* __restrict__ ei,
                       const float* __restrict__ b1, const float* __restrict__ ln_g,
                       const float* __restrict__ ln_b, const float* __restrict__ W2,
                       const float* __restrict__ b2, float* __restrict__ out, int e_cnt) {
    const int EPW = 8;
    int lane = threadIdx.x & 31, warp = threadIdx.x >> 5;
    int base = (blockIdx.x * 8 + warp) * EPW;
    if (base >= e_cnt) return;
    int cnt = min(EPW, e_cnt - base);
    float w2a[10], w2b[10];
    #pragma unroll
    for (int c = 0; c < 10; c++) {
        w2a[c] = W2[(2 * lane) * 10 + c];
        w2b[c] = W2[(2 * lane + 1) * 10 + c];
    }
    float2 b1v = ((const float2*)b1)[lane];
    float2 gv  = ((const float2*)ln_g)[lane];
    float2 bv  = ((const float2*)ln_b)[lane];
    float myb2 = (lane < 10) ? b2[lane] : 0.f;
    const float2* A2 = (const float2*)g_A;
    const float2* B2 = (const float2*)g_B;
    // prefetch all indices first so the A/B gathers across edges are independent
    int s_arr[EPW], d_arr[EPW];
    #pragma unroll
    for (int t = 0; t < EPW; t++) {
        if (t < cnt) { s_arr[t] = ei[base + t]; d_arr[t] = ei[e_cnt + base + t]; }
    }
    #pragma unroll
    for (int t = 0; t < EPW; t++) {
        if (t >= cnt) break;
        int e = base + t;
        float2 za = A2[s_arr[t] * 32 + lane];
        float2 zb = B2[d_arr[t] * 32 + lane];
        float zx = za.x + zb.x + b1v.x;
        float zy = za.y + zb.y + b1v.y;
        float sum = zx + zy;
        float sq = zx * zx + zy * zy;
        #pragma unroll
        for (int o = 16; o; o >>= 1) {
            sum += __shfl_xor_sync(0xffffffffu, sum, o);
            sq  += __shfl_xor_sync(0xffffffffu, sq, o);
        }
        float mu = sum * (1.f / 64.f);
        float var = sq * (1.f / 64.f) - mu * mu;
        float inv = rsqrtf(var + 1e-5f);
        zx = fmaxf((zx - mu) * inv * gv.x + bv.x, 0.f);
        zy = fmaxf((zy - mu) * inv * gv.y + bv.y, 0.f);
        float res = 0.f;
        #pragma unroll
        for (int c = 0; c < 10; c++) {
            float p = zx * w2a[c] + zy * w2b[c];
            #pragma unroll
            for (int o = 16; o; o >>= 1) p += __shfl_xor_sync(0xffffffffu, p, o);
            if (lane == c) res = p + myb2;
        }
        if (lane < 10) out[e * 10 + lane] = res;
    }
}

// ---------------- host launcher ----------------
extern "C" void kernel_launch(void* const* d_in, const int* in_sizes, int n_in,
                              void* d_out, int out_size) {
    const float* x     = (const float*)d_in[0];
    const float* W_lin = (const float*)d_in[1];
    const float* b_lin = (const float*)d_in[2];
    const float* Ws    = (const float*)d_in[3];
    const float* W1    = (const float*)d_in[4];
    const float* b1    = (const float*)d_in[5];
    const float* ln_g  = (const float*)d_in[6];
    const float* ln_b  = (const float*)d_in[7];
    const float* W2    = (const float*)d_in[8];
    const float* b2    = (const float*)d_in[9];
    const int*   ei    = (const int*)d_in[10];
    float* out = (float*)d_out;

    int n = in_sizes[0] / H;        // 50000
    int e = in_sizes[10] / 2;       // 1600000
    int nb = (n + 255) / 256;       // scan blocks (<=256)

    float *p_h, *p_h0, *p_tmp;
    int *p_deg, *p_rowcnt;
    cudaGetSymbolAddress((void**)&p_h, g_h);
    cudaGetSymbolAddress((void**)&p_h0, g_h0);
    cudaGetSymbolAddress((void**)&p_tmp, g_tmp);
    cudaGetSymbolAddress((void**)&p_deg, g_deg);
    cudaGetSymbolAddress((void**)&p_rowcnt, g_rowcnt);

    // CSR + normalization build
    cudaMemsetAsync(p_deg, 0, n * sizeof(int));
    cudaMemsetAsync(p_rowcnt, 0, n * sizeof(int));
    k_count<<<(e + 255) / 256, 256>>>(ei, e);
    k_dinv<<<(n + 255) / 256, 256>>>(n);
    k_scan1<<<nb, 256>>>(n);
    k_scan2<<<1, 256>>>(nb, e, n);
    k_scan3<<<nb, 256>>>(n);
    k_csr_fill<<<(e + 255) / 256, 256>>>(ei, e);

    // h = relu(x @ W_lin + b_lin); h0 = h
    k_gemm64<<<(n + 63) / 64, 256>>>(x, W_lin, b_lin, p_h, p_h0, n);

    // 8 fused SpMM+GEMM layers, double-buffered
    const int LGRID = 1184;
    float* bufs[2] = { p_h, p_tmp };
    for (int l = 0; l < 8; l++) {
        float beta = (float)log(0.5 / (double)(l + 1) + 1.0);
        k_layer<<<LGRID, 256>>>(bufs[l & 1], bufs[(l + 1) & 1], Ws + l * 4096, beta, n);
    }
    // after 8 layers (even count) final h is back in g_h

    // A = h @ W1[:64], B = h @ W1[64:]
    k_ab<<<LGRID, 256>>>(p_h, W1, n);

    // per-edge MLP head
    k_edge<<<(e + 63) / 64, 256>>>(ei, b1, ln_g, ln_b, W2, b2, out, e);
}